// round 8
// baseline (speedup 1.0000x reference)
#include <cuda_runtime.h>
#include <cuda_fp16.h>
#include <cstdint>

// out = tanh(x @ W^T + b); x (131072, 256) fp32, W (256,256) fp32, b (256).
//
// mma.sync m16n8k16 f16->f32 (compute_103-portable). 512 threads / 16 warps;
// warp (p = w&7, h = w>>3) owns n-slice [p*32,p*32+32) x K-half
// [h*128,h*128+128): W = 64 regs, acc = 32 regs -> 4 warps/SMSP.
//
// Round-8 vs r7 (L1 was the binding pipe; exchange cost ~1536 cyc/tile):
//   - half-exchange: warp keeps acc[h] (its own epilogue tokens) in regs,
//     writes ONLY acc[1-h] to the pair scratch; reads partner's half. 64KB
//     exchange traffic/tile instead of 128KB.
//   - parity-disjoint swizzle (chunk ^ 2*(row&3)): conflict-free STS.64/LDS.64
//     per half-warp phase.
//   - epilogue: regs + lds64 partner partials, tanh, frag-layout STG.64
//     (sector-equivalent to coalesced).

#define HID      256
#define MT       32
#define NT       4096
#define GRID     148
#define NTHREADS 512

// SMEM (bytes): 2 fp32 stages (32KB ea), 2 fp16 bufs (16KB ea),
// exchange scratch 8 pairs x 4KB = 32KB.
#define SM_S0    0u
#define SM_S1    32768u
#define SM_B0    65536u
#define SM_B1    81920u
#define SM_SCR   98304u
#define SMEM_TOTAL (98304 + 32768)

// ---------------------------------------------------------------- helpers ----

__device__ __forceinline__ uint32_t smem_u32(const void* p) {
    uint32_t a;
    asm("{ .reg .u64 t; cvta.to.shared.u64 t, %1; cvt.u32.u64 %0, t; }"
        : "=r"(a) : "l"(p));
    return a;
}

__device__ __forceinline__ void cp_async16(uint32_t dst, const void* src) {
    asm volatile("cp.async.cg.shared.global [%0], [%1], 16;"
                 :: "r"(dst), "l"(src) : "memory");
}
__device__ __forceinline__ void cp_commit() {
    asm volatile("cp.async.commit_group;" ::: "memory");
}
__device__ __forceinline__ void cp_wait0() {
    asm volatile("cp.async.wait_group 0;" ::: "memory");
}
__device__ __forceinline__ void cp_wait1() {
    asm volatile("cp.async.wait_group 1;" ::: "memory");
}

__device__ __forceinline__ void sts64(uint32_t addr, uint32_t a, uint32_t b) {
    asm volatile("st.shared.v2.u32 [%0], {%1, %2};" :: "r"(addr), "r"(a), "r"(b));
}
__device__ __forceinline__ void sts64f(uint32_t addr, float a, float b) {
    asm volatile("st.shared.v2.f32 [%0], {%1, %2};" :: "r"(addr), "f"(a), "f"(b));
}
__device__ __forceinline__ void lds64f(float* v, uint32_t addr) {
    asm volatile("ld.shared.v2.f32 {%0, %1}, [%2];"
                 : "=f"(v[0]), "=f"(v[1]) : "r"(addr));
}
__device__ __forceinline__ void lds128(uint32_t* r, uint32_t addr) {
    asm volatile("ld.shared.v4.u32 {%0, %1, %2, %3}, [%4];"
                 : "=r"(r[0]), "=r"(r[1]), "=r"(r[2]), "=r"(r[3]) : "r"(addr));
}

__device__ __forceinline__ void ldsm_x4(uint32_t* r, uint32_t addr) {
    asm volatile("ldmatrix.sync.aligned.m8n8.x4.shared.b16 {%0, %1, %2, %3}, [%4];"
                 : "=r"(r[0]), "=r"(r[1]), "=r"(r[2]), "=r"(r[3]) : "r"(addr));
}

__device__ __forceinline__ void mma16816(float* d, const uint32_t* a,
                                         const uint32_t* bfr) {
    asm volatile(
        "mma.sync.aligned.m16n8k16.row.col.f32.f16.f16.f32 "
        "{%0, %1, %2, %3}, {%4, %5, %6, %7}, {%8, %9}, {%0, %1, %2, %3};"
        : "+f"(d[0]), "+f"(d[1]), "+f"(d[2]), "+f"(d[3])
        : "r"(a[0]), "r"(a[1]), "r"(a[2]), "r"(a[3]), "r"(bfr[0]), "r"(bfr[1]));
}

__device__ __forceinline__ float tanh_f(float y) {
    float r;
    asm("tanh.approx.f32 %0, %1;" : "=f"(r) : "f"(y));
    return r;
}

__device__ __forceinline__ void bar_pair(int id) {
    asm volatile("bar.sync %0, 64;" :: "r"(id) : "memory");
}

// coalesced cp.async of one 32-token fp32 tile (32KB) into a stage
__device__ __forceinline__ void fill_stage(const float* __restrict__ x, int t,
                                           uint32_t stage, int tid) {
#pragma unroll
    for (int i = 0; i < 4; i++) {
        int g = tid + i * NTHREADS;
        cp_async16(stage + (uint32_t)g * 16u,
                   (const char*)(x + (size_t)t * MT * HID) + (size_t)g * 16);
    }
}

// fp32 stage -> fp16 buffer (ldmatrix-swizzled: 32 rows x 512B)
__device__ __forceinline__ void convert_tile(uint32_t src, uint32_t dst, int tid) {
#pragma unroll
    for (int i = 0; i < 4; i++) {
        int g = tid + i * NTHREADS;
        uint32_t r[4];
        lds128(r, src + (uint32_t)g * 16u);
        __half2 h0 = __floats2half2_rn(__uint_as_float(r[0]), __uint_as_float(r[1]));
        __half2 h1 = __floats2half2_rn(__uint_as_float(r[2]), __uint_as_float(r[3]));
        uint32_t row = (uint32_t)(g >> 6);
        uint32_t c4  = (uint32_t)(g & 63);
        uint32_t c16 = c4 >> 1;
        uint32_t a = dst + row * 512u + ((c16 ^ (row & 7u)) << 4) + (c4 & 1u) * 8u;
        sts64(a, *(const uint32_t*)&h0, *(const uint32_t*)&h1);
    }
}

// ----------------------------------------------------------------- kernel ----

__global__ void __launch_bounds__(NTHREADS, 1)
rotor_kernel(const float* __restrict__ x, const float* __restrict__ W,
             const float* __restrict__ b, float* __restrict__ out) {
    extern __shared__ char smem[];
    const uint32_t sb = smem_u32(smem);
    const int tid = threadIdx.x;
    const int w = tid >> 5;
    const int l = tid & 31;
    const int p = w & 7;       // n-slice / pair id
    const int h = w >> 3;      // K-half (also this warp's epilogue token half)

    const int t0 = blockIdx.x;

    // --- two fills in flight before anything waits
    fill_stage(x, t0, sb + SM_S0, tid);
    cp_commit();
    fill_stage(x, t0 + GRID, sb + SM_S1, tid);   // t0+GRID < NT always
    cp_commit();

    // --- W -> registers (under fill latency). n = p*32+na*8+(l>>2),
    // k = h*128+ks*16+(l&3)*2 (m16n8k16 B frag, col-major).
    uint32_t wreg[4][8][2];
    {
        const float2* Wv = (const float2*)W;
        const int nb = p * 32 + (l >> 2);
        const int kb = h * 128 + (l & 3) * 2;
#pragma unroll
        for (int na = 0; na < 4; na++) {
            const int n = nb + na * 8;
#pragma unroll
            for (int ks = 0; ks < 8; ks++) {
                const int k = kb + ks * 16;
                float2 f0 = Wv[n * 128 + (k >> 1)];
                float2 f1 = Wv[n * 128 + ((k + 8) >> 1)];
                __half2 h0 = __floats2half2_rn(f0.x, f0.y);
                __half2 h1 = __floats2half2_rn(f1.x, f1.y);
                wreg[na][ks][0] = *(const uint32_t*)&h0;
                wreg[na][ks][1] = *(const uint32_t*)&h1;
            }
        }
    }
    // bias in frag layout: cols n, n+1 for each na
    float2 bb[4];
#pragma unroll
    for (int na = 0; na < 4; na++)
        bb[na] = *(const float2*)&b[p * 32 + na * 8 + (l & 3) * 2];

    // pair scratch (4KB): token-major rows of 128B. 8B slot for (na, l&3) at
    // chunk = na*2 + ((l&3)>>1), hb = (l&3 & 1)*8, swizzled by 2*(row&3)
    // (parity-disjoint -> conflict-free per half-warp phase).
    const uint32_t scrp = sb + SM_SCR + (uint32_t)p * 4096u;
    const uint32_t chunk = (uint32_t)(((l & 3) >> 1));   // + na*2 added per na
    const uint32_t hb = ((uint32_t)l & 1u) << 3;
    const uint32_t rsw = 2u * (((uint32_t)l >> 2) & 3u); // = 2*(row&3)

    // --- convert tile t0 (own chunks only -> cp_wait1 suffices)
    cp_wait1();
    convert_tile(sb + SM_S0, sb + SM_B0, tid);

    int iter = 0;
    for (int t = t0; t < NT; t += GRID, iter++) {
        const uint32_t bufg = sb + ((iter & 1) ? SM_B1 : SM_B0);   // GEMM src
        const uint32_t bufc = sb + ((iter & 1) ? SM_B0 : SM_B1);   // convert dst
        const uint32_t stf  = sb + ((iter & 1) ? SM_S1 : SM_S0);   // fill dst
        const uint32_t stc  = sb + ((iter & 1) ? SM_S0 : SM_S1);   // convert src
        const bool have_next = (t + GRID) < NT;

        cp_wait0();          // fill(t+1) arrived (committed one iter ago)
        // Orders buffer reuse, cp.async visibility, and all scratch reads of
        // the previous iteration before this iteration's scratch writes.
        __syncthreads();

        if (t + 2 * GRID < NT) fill_stage(x, t + 2 * GRID, stf, tid);
        cp_commit();
        if (have_next) convert_tile(stc, bufc, tid);

        // --- GEMM: m 0..31 x n-slice 32 x this warp's K-half
        float acc[2][4][4];
#pragma unroll
        for (int ma = 0; ma < 2; ma++)
#pragma unroll
            for (int na = 0; na < 4; na++)
#pragma unroll
                for (int c = 0; c < 4; c++) acc[ma][na][c] = 0.0f;

#pragma unroll
        for (int ks = 0; ks < 8; ks++) {
            uint32_t af[2][4];
#pragma unroll
            for (int ma = 0; ma < 2; ma++) {
                const uint32_t row = (uint32_t)(ma * 16 + (l & 15));
                const uint32_t c16 = (uint32_t)(h * 16 + ks * 2 + (l >> 4));
                ldsm_x4(af[ma], bufg + row * 512u + ((c16 ^ (row & 7u)) << 4));
            }
#pragma unroll
            for (int ma = 0; ma < 2; ma++)
#pragma unroll
                for (int na = 0; na < 4; na++)
                    mma16816(acc[ma][na], af[ma], wreg[na][ks]);
        }

        // --- half-exchange: write partner-half partials acc[1-h] only.
        // rows r1 = (1-h)*16 + (l>>2), r2 = r1 + 8  (r&3 identical for both).
        {
            const int mo = 1 - h;
            const uint32_t r1 = (uint32_t)(mo * 16 + (l >> 2));
            const uint32_t r2 = r1 + 8u;
#pragma unroll
            for (int na = 0; na < 4; na++) {
                const uint32_t ce = (((uint32_t)(na * 2) + chunk) ^ rsw) & 7u;
                sts64f(scrp + r1 * 128u + (ce << 4) + hb,
                       acc[mo][na][0], acc[mo][na][1]);
                sts64f(scrp + r2 * 128u + (ce << 4) + hb,
                       acc[mo][na][2], acc[mo][na][3]);
            }
        }
        bar_pair(p + 1);

        // --- epilogue for own tokens (ma = h): regs + partner partials
        {
            const uint32_t r1 = (uint32_t)(h * 16 + (l >> 2));
            const uint32_t r2 = r1 + 8u;
            const size_t ob = (size_t)(t * MT) * HID + p * 32 + (l & 3) * 2;
#pragma unroll
            for (int na = 0; na < 4; na++) {
                const uint32_t ce = (((uint32_t)(na * 2) + chunk) ^ rsw) & 7u;
                float q01[2], q23[2];
                lds64f(q01, scrp + r1 * 128u + (ce << 4) + hb);
                lds64f(q23, scrp + r2 * 128u + (ce << 4) + hb);
                float2 v0, v1;
                v0.x = tanh_f(acc[h][na][0] + q01[0] + bb[na].x);
                v0.y = tanh_f(acc[h][na][1] + q01[1] + bb[na].y);
                v1.x = tanh_f(acc[h][na][2] + q23[0] + bb[na].x);
                v1.y = tanh_f(acc[h][na][3] + q23[1] + bb[na].y);
                __stcs((float2*)&out[ob + (size_t)r1 * HID + na * 8], v0);
                __stcs((float2*)&out[ob + (size_t)r2 * HID + na * 8], v1);
            }
        }
    }
}

// ----------------------------------------------------------------- launch ----

extern "C" void kernel_launch(void* const* d_in, const int* in_sizes, int n_in,
                              void* d_out, int out_size) {
    const float* x = (const float*)d_in[0];
    const float* W = (const float*)d_in[1];
    const float* b = (const float*)d_in[2];
    float* out = (float*)d_out;
    cudaFuncSetAttribute(rotor_kernel,
                         cudaFuncAttributeMaxDynamicSharedMemorySize, SMEM_TOTAL);
    rotor_kernel<<<GRID, NTHREADS, SMEM_TOTAL>>>(x, W, b, out);
}

// round 12
// speedup vs baseline: 1.3497x; 1.3497x over previous
#include <cuda_runtime.h>
#include <cuda_fp16.h>
#include <cstdint>

// out = tanh(x @ W^T + b); x (131072, 256) fp32, W (256,256) fp32, b (256).
//
// mma.sync m16n8k16 f16->f32 (compute_103-portable). 256 threads / 8 warps,
// W fp16 register-stationary, 64-token tiles, persistent 148 CTAs.
// r5 core (passed, 65.6us): cp.async fp32 double-stage, fp32->fp16 convert
// interleaved into the first 16 GEMM steps, flattened 64-step GEMM with
// 2-deep ldsm rotation. Epilogue = store bounce: raw accs STS'd (windowed
// XOR swizzle) into the dead convert-source stage, then coalesced LDS.128 +
// bias + tanh + STG.128.
//
// r11 bug fixed: epilogue loop must cover 4096 16B chunks (16 per thread),
// not 1024 — rows 16..63 were never stored (rel_err 0.866 = sqrt(48/64)).

#define HID      256
#define MT       64
#define NT       2048
#define GRID     148
#define NTHREADS 256

// SMEM map (bytes): 2 fp32 stages (64KB ea), 2 fp16 bufs (32KB ea) = 192KB.
// The bounce reuses the convert-source stage (stc) each iteration.
#define SM_S0    0u
#define SM_S1    65536u
#define SM_B0    131072u
#define SM_B1    163840u
#define SMEM_TOTAL (2 * 65536 + 2 * 32768)

// ---------------------------------------------------------------- helpers ----

__device__ __forceinline__ uint32_t smem_u32(const void* p) {
    uint32_t a;
    asm("{ .reg .u64 t; cvta.to.shared.u64 t, %1; cvt.u32.u64 %0, t; }"
        : "=r"(a) : "l"(p));
    return a;
}

__device__ __forceinline__ void cp_async16(uint32_t dst, const void* src) {
    asm volatile("cp.async.cg.shared.global [%0], [%1], 16;"
                 :: "r"(dst), "l"(src) : "memory");
}
__device__ __forceinline__ void cp_commit() {
    asm volatile("cp.async.commit_group;" ::: "memory");
}
__device__ __forceinline__ void cp_wait0() {
    asm volatile("cp.async.wait_group 0;" ::: "memory");
}
__device__ __forceinline__ void cp_wait1() {
    asm volatile("cp.async.wait_group 1;" ::: "memory");
}

__device__ __forceinline__ void sts64(uint32_t addr, uint32_t a, uint32_t b) {
    asm volatile("st.shared.v2.u32 [%0], {%1, %2};" :: "r"(addr), "r"(a), "r"(b));
}
__device__ __forceinline__ void sts64f(uint32_t addr, float a, float b) {
    asm volatile("st.shared.v2.f32 [%0], {%1, %2};" :: "r"(addr), "f"(a), "f"(b));
}
__device__ __forceinline__ void lds128f(float* v, uint32_t addr) {
    asm volatile("ld.shared.v4.f32 {%0, %1, %2, %3}, [%4];"
                 : "=f"(v[0]), "=f"(v[1]), "=f"(v[2]), "=f"(v[3]) : "r"(addr));
}
__device__ __forceinline__ void lds128(uint32_t* r, uint32_t addr) {
    asm volatile("ld.shared.v4.u32 {%0, %1, %2, %3}, [%4];"
                 : "=r"(r[0]), "=r"(r[1]), "=r"(r[2]), "=r"(r[3]) : "r"(addr));
}

__device__ __forceinline__ void ldsm_x4(uint32_t* r, uint32_t addr) {
    asm volatile("ldmatrix.sync.aligned.m8n8.x4.shared.b16 {%0, %1, %2, %3}, [%4];"
                 : "=r"(r[0]), "=r"(r[1]), "=r"(r[2]), "=r"(r[3]) : "r"(addr));
}

__device__ __forceinline__ void mma16816(float* d, const uint32_t* a,
                                         const uint32_t* bfr) {
    asm volatile(
        "mma.sync.aligned.m16n8k16.row.col.f32.f16.f16.f32 "
        "{%0, %1, %2, %3}, {%4, %5, %6, %7}, {%8, %9}, {%0, %1, %2, %3};"
        : "+f"(d[0]), "+f"(d[1]), "+f"(d[2]), "+f"(d[3])
        : "r"(a[0]), "r"(a[1]), "r"(a[2]), "r"(a[3]), "r"(bfr[0]), "r"(bfr[1]));
}

__device__ __forceinline__ float tanh_f(float y) {
    float r;
    asm("tanh.approx.f32 %0, %1;" : "=f"(r) : "f"(y));
    return r;
}

// coalesced 16B cp.async fill of one fp32 tile into a stage
__device__ __forceinline__ void fill_stage(const float* __restrict__ x, int t,
                                           uint32_t stage, int tid) {
    const char* src = (const char*)(x + (size_t)t * MT * HID);
#pragma unroll
    for (int i = 0; i < 16; i++) {
        int g = tid + i * NTHREADS;
        cp_async16(stage + (uint32_t)g * 16u, src + (size_t)g * 16);
    }
}

// one 1/16 slice of the fp32->fp16 convert (ldmatrix-swizzled dest)
__device__ __forceinline__ void convert_chunk(uint32_t src, uint32_t dst,
                                              int tid, int i) {
    int g = tid + i * NTHREADS;
    uint32_t r[4];
    lds128(r, src + (uint32_t)g * 16u);
    __half2 h0 = __floats2half2_rn(__uint_as_float(r[0]), __uint_as_float(r[1]));
    __half2 h1 = __floats2half2_rn(__uint_as_float(r[2]), __uint_as_float(r[3]));
    uint32_t row = (uint32_t)(g >> 6);
    uint32_t c4  = (uint32_t)(g & 63);
    uint32_t c16 = c4 >> 1;
    uint32_t addr = dst + row * 512u + ((c16 ^ (row & 7u)) << 4) + (c4 & 1u) * 8u;
    sts64(addr, *(const uint32_t*)&h0, *(const uint32_t*)&h1);
}

// ----------------------------------------------------------------- kernel ----

__global__ void __launch_bounds__(NTHREADS, 1)
rotor_kernel(const float* __restrict__ x, const float* __restrict__ W,
             const float* __restrict__ b, float* __restrict__ out) {
    extern __shared__ char smem[];
    const uint32_t sb = smem_u32(smem);
    const int tid = threadIdx.x;
    const int w = tid >> 5;
    const int l = tid & 31;

    const int t0 = blockIdx.x;

    // --- prologue: two fills in flight before anything waits
    fill_stage(x, t0, sb + SM_S0, tid);
    cp_commit();
    fill_stage(x, t0 + GRID, sb + SM_S1, tid);   // t0+GRID < NT always
    cp_commit();

    // --- W -> registers (hidden under fill latency). Warp w owns n in
    // [w*32, w*32+32). B frag (m16n8k16 col): b0={W[n][k],W[n][k+1]},
    // b1={W[n][k+8],W[n][k+9]}; n = w*32+na*8+(l>>2), k = ks*16+(l&3)*2.
    uint32_t wreg[4][16][2];
    {
        const float2* Wv = (const float2*)W;
        const int nb = w * 32 + (l >> 2);
        const int kb = (l & 3) * 2;
#pragma unroll
        for (int na = 0; na < 4; na++) {
            const int n = nb + na * 8;
#pragma unroll
            for (int ks = 0; ks < 16; ks++) {
                const int k = ks * 16 + kb;
                float2 f0 = Wv[n * 128 + (k >> 1)];
                float2 f1 = Wv[n * 128 + ((k + 8) >> 1)];
                __half2 h0 = __floats2half2_rn(f0.x, f0.y);
                __half2 h1 = __floats2half2_rn(f1.x, f1.y);
                wreg[na][ks][0] = *(const uint32_t*)&h0;
                wreg[na][ks][1] = *(const uint32_t*)&h1;
            }
        }
    }

    // --- convert tile t0 (stage0); own chunks only -> cp_wait1 suffices
    cp_wait1();
#pragma unroll
    for (int i = 0; i < 16; i++)
        convert_chunk(sb + SM_S0, sb + SM_B0, tid, i);

    int iter = 0;
    for (int t = t0; t < NT; t += GRID, iter++) {
        const uint32_t bufg = sb + ((iter & 1) ? SM_B1 : SM_B0);          // GEMM src
        const uint32_t bufc = sb + ((iter & 1) ? SM_B0 : SM_B1);          // convert dst
        const uint32_t stc  = sb + ((iter & 1) ? SM_S0 : SM_S1);          // convert src
        const uint32_t stf  = sb + ((iter & 1) ? SM_S1 : SM_S0);          // fill dst
        const bool have_next = (t + GRID) < NT;

        cp_wait0();          // fill(t+1) arrived (committed one iter ago)
        // Orders: buffer/stage reuse (incl. last iter's bounce reads of the
        // region that is now stf), convert STS visibility, cp.async data.
        __syncthreads();

        if (t + 2 * GRID < NT) fill_stage(x, t + 2 * GRID, stf, tid);
        cp_commit();

        float acc[4][4][4];
#pragma unroll
        for (int ma = 0; ma < 4; ma++)
#pragma unroll
            for (int na = 0; na < 4; na++)
#pragma unroll
                for (int c = 0; c < 4; c++) acc[ma][na][c] = 0.0f;

        // --- flattened 64-step pipeline: j = ma*16 + ks; convert(t+1) woven
        // into the first 16 steps.
        uint32_t af[2][4];
        {
            const uint32_t row = (uint32_t)(l & 15);
            const uint32_t c16 = (uint32_t)(l >> 4);
            ldsm_x4(af[0], bufg + row * 512u + ((c16 ^ (row & 7u)) << 4));
        }
#pragma unroll
        for (int j = 0; j < 64; j++) {
            const int ks = j & 15;
            if (j < 63) {
                const int jn = j + 1;
                const uint32_t row = (uint32_t)(((jn >> 4) << 4) + (l & 15));
                const uint32_t c16 = (uint32_t)(((jn & 15) << 1) + (l >> 4));
                ldsm_x4(af[jn & 1], bufg + row * 512u + ((c16 ^ (row & 7u)) << 4));
            }
            if ((j >> 4) == 0 && have_next) convert_chunk(stc, bufc, tid, ks);
#pragma unroll
            for (int na = 0; na < 4; na++)
                mma16816(acc[j >> 4][na], af[j & 1], wreg[na][ks]);
        }

        // All warps' convert reads of stc (and ldsm of bufg) done -> stc is
        // dead fp32 data, reusable as the store bounce.
        __syncthreads();

        // --- bounce: raw accs -> stc (64 rows x 1024B; warp window w*128B;
        // window chunk c = na*2 + ((l&3)>>1), XOR-swizzled by row&7)
        {
            const uint32_t wbase = stc + (uint32_t)w * 128u;
            const uint32_t cfix  = ((uint32_t)(l & 3) >> 1);
            const uint32_t hb    = ((uint32_t)l & 1u) << 3;
#pragma unroll
            for (int ma = 0; ma < 4; ma++) {
                const uint32_t r1 = (uint32_t)(ma * 16 + (l >> 2));
                const uint32_t r2 = r1 + 8u;
#pragma unroll
                for (int na = 0; na < 4; na++) {
                    const uint32_t c = (uint32_t)(na * 2) + cfix;
                    sts64f(wbase + r1 * 1024u + ((c ^ (r1 & 7u)) << 4) + hb,
                           acc[ma][na][0], acc[ma][na][1]);
                    sts64f(wbase + r2 * 1024u + ((c ^ (r2 & 7u)) << 4) + hb,
                           acc[ma][na][2], acc[ma][na][3]);
                }
            }
        }
        __syncthreads();

        // --- coalesced epilogue: 16 chunks/thread (4096 total = 64 rows x 64)
        const size_t ob = (size_t)t * MT * HID;
#pragma unroll
        for (int jj = 0; jj < 16; jj++) {
            const int g = tid + jj * NTHREADS;     // 0..4095
            const uint32_t row = (uint32_t)(g >> 6);
            const uint32_t c16 = (uint32_t)(g & 63);
            const uint32_t wp  = c16 >> 3;
            const uint32_t wc  = c16 & 7u;
            float v[4];
            lds128f(v, stc + row * 1024u + wp * 128u + ((wc ^ (row & 7u)) << 4));
            const float4 bv = __ldg(&((const float4*)b)[c16]);
            float4 o;
            o.x = tanh_f(v[0] + bv.x);
            o.y = tanh_f(v[1] + bv.y);
            o.z = tanh_f(v[2] + bv.z);
            o.w = tanh_f(v[3] + bv.w);
            __stcs((float4*)&out[ob + (size_t)row * HID + c16 * 4], o);
        }
    }
}

// ----------------------------------------------------------------- launch ----

extern "C" void kernel_launch(void* const* d_in, const int* in_sizes, int n_in,
                              void* d_out, int out_size) {
    const float* x = (const float*)d_in[0];
    const float* W = (const float*)d_in[1];
    const float* b = (const float*)d_in[2];
    float* out = (float*)d_out;
    cudaFuncSetAttribute(rotor_kernel,
                         cudaFuncAttributeMaxDynamicSharedMemorySize, SMEM_TOTAL);
    rotor_kernel<<<GRID, NTHREADS, SMEM_TOTAL>>>(x, W, b, out);
}

// round 13
// speedup vs baseline: 1.3759x; 1.0195x over previous
#include <cuda_runtime.h>
#include <cuda_fp16.h>
#include <cstdint>

// out = tanh(x @ W^T + b); x (131072, 256) fp32, W (256,256) fp32, b (256).
//
// mma.sync m16n8k16 f16->f32 (compute_103-portable). 256 threads / 8 warps,
// W fp16 register-stationary (warp owns 32-wide n-slice, full K), 64-token
// tiles, persistent 148 CTAs. r5 skeleton (proven 65.6us): single barrier
// per iter, flattened 64-step GEMM with 2-deep ldsm rotation, epilogue of
// m-atom (ma-1) interleaved into steps of ma.
//
// Change vs r5: cp.async fp32 double-stage REMOVED. Next tile is fetched by
// direct LDG.128 -> cvt -> swizzled fp16 STS, woven into the ma=0 GEMM steps
// (LDG batches at j=0/12/24/36, cvt+STS at j=8/20/32/44). This deletes the
// stage round-trip from the binding L1 pipe. (This weave was exonerated by
// the r12 bisect: the r9/r10 failures were an epilogue loop-bound bug.)

#define HID      256
#define MT       64
#define NT       2048
#define GRID     148
#define NTHREADS 256

// SMEM: two fp16 ldmatrix-swizzled buffers (32KB each)
#define SM_B0    0u
#define SM_B1    32768u
#define SMEM_TOTAL 65536

// ---------------------------------------------------------------- helpers ----

__device__ __forceinline__ uint32_t smem_u32(const void* p) {
    uint32_t a;
    asm("{ .reg .u64 t; cvta.to.shared.u64 t, %1; cvt.u32.u64 %0, t; }"
        : "=r"(a) : "l"(p));
    return a;
}

__device__ __forceinline__ void sts64(uint32_t addr, uint32_t a, uint32_t b) {
    asm volatile("st.shared.v2.u32 [%0], {%1, %2};" :: "r"(addr), "r"(a), "r"(b));
}

__device__ __forceinline__ void ldsm_x4(uint32_t* r, uint32_t addr) {
    asm volatile("ldmatrix.sync.aligned.m8n8.x4.shared.b16 {%0, %1, %2, %3}, [%4];"
                 : "=r"(r[0]), "=r"(r[1]), "=r"(r[2]), "=r"(r[3]) : "r"(addr));
}

__device__ __forceinline__ void mma16816(float* d, const uint32_t* a,
                                         const uint32_t* bfr) {
    asm volatile(
        "mma.sync.aligned.m16n8k16.row.col.f32.f16.f16.f32 "
        "{%0, %1, %2, %3}, {%4, %5, %6, %7}, {%8, %9}, {%0, %1, %2, %3};"
        : "+f"(d[0]), "+f"(d[1]), "+f"(d[2]), "+f"(d[3])
        : "r"(a[0]), "r"(a[1]), "r"(a[2]), "r"(a[3]), "r"(bfr[0]), "r"(bfr[1]));
}

__device__ __forceinline__ float tanh_f(float y) {
    float r;
    asm("tanh.approx.f32 %0, %1;" : "=f"(r) : "f"(y));
    return r;
}

// convert one float4 (reg) -> fp16 swizzled buffer slot for float4-index g
__device__ __forceinline__ void cvt_store(uint32_t dst, int g, float4 v) {
    __half2 h0 = __floats2half2_rn(v.x, v.y);
    __half2 h1 = __floats2half2_rn(v.z, v.w);
    uint32_t row = (uint32_t)(g >> 6);        // 64 float4 per 256-col row
    uint32_t c4  = (uint32_t)(g & 63);
    uint32_t c16 = c4 >> 1;
    uint32_t a = dst + row * 512u + ((c16 ^ (row & 7u)) << 4) + (c4 & 1u) * 8u;
    sts64(a, *(const uint32_t*)&h0, *(const uint32_t*)&h1);
}

// ----------------------------------------------------------------- kernel ----

__global__ void __launch_bounds__(NTHREADS, 1)
rotor_kernel(const float* __restrict__ x, const float* __restrict__ W,
             const float* __restrict__ b, float* __restrict__ out) {
    extern __shared__ char smem[];
    const uint32_t sb = smem_u32(smem);
    const int tid = threadIdx.x;
    const int w = tid >> 5;
    const int l = tid & 31;

    const int t0 = blockIdx.x;

    // --- W -> registers. Warp w owns n in [w*32, w*32+32), full K.
    // B frag (m16n8k16 col): b0={W[n][k],W[n][k+1]}, b1={W[n][k+8],W[n][k+9]};
    // n = w*32+na*8+(l>>2), k = ks*16+(l&3)*2.
    uint32_t wreg[4][16][2];
    {
        const float2* Wv = (const float2*)W;
        const int nb = w * 32 + (l >> 2);
        const int kb = (l & 3) * 2;
#pragma unroll
        for (int na = 0; na < 4; na++) {
            const int n = nb + na * 8;
#pragma unroll
            for (int ks = 0; ks < 16; ks++) {
                const int k = ks * 16 + kb;
                float2 f0 = Wv[n * 128 + (k >> 1)];
                float2 f1 = Wv[n * 128 + ((k + 8) >> 1)];
                __half2 h0 = __floats2half2_rn(f0.x, f0.y);
                __half2 h1 = __floats2half2_rn(f1.x, f1.y);
                wreg[na][ks][0] = *(const uint32_t*)&h0;
                wreg[na][ks][1] = *(const uint32_t*)&h1;
            }
        }
    }
    // bias for this thread's output columns (frag layout)
    float2 bb[4];
    {
        const int n = w * 32 + (l & 3) * 2;
#pragma unroll
        for (int na = 0; na < 4; na++)
            bb[na] = *(const float2*)&b[n + na * 8];
    }

    // per-thread fixed output base: row (l>>2), col w*32+(l&3)*2
    float* const obase = out + (size_t)(l >> 2) * HID + w * 32 + (l & 3) * 2;

    // --- prologue: tile t0 -> fp16 buf0 (direct LDG -> cvt -> STS)
    {
        const float4* src = (const float4*)(x + (size_t)t0 * MT * HID);
#pragma unroll
        for (int i = 0; i < 16; i += 4) {
            float4 v[4];
#pragma unroll
            for (int k = 0; k < 4; k++)
                v[k] = __ldcs(&src[tid + (i + k) * NTHREADS]);
#pragma unroll
            for (int k = 0; k < 4; k++)
                cvt_store(sb + SM_B0, tid + (i + k) * NTHREADS, v[k]);
        }
    }

    int iter = 0;
    for (int t = t0; t < NT; t += GRID, iter++) {
        const uint32_t bufg = sb + ((iter & 1) ? SM_B1 : SM_B0);   // GEMM src
        const uint32_t bufc = sb + ((iter & 1) ? SM_B0 : SM_B1);   // cvt dst (t+1)
        const bool have_next = (t + GRID) < NT;
        const float4* nsrc = (const float4*)(x + (size_t)(t + GRID) * MT * HID);

        // Single barrier per iter: orders prev iter's STS of bufg before this
        // iter's ldsm (and the prologue STS on iter 0), and prev ldsm of bufc
        // before this iter's STS into it.
        __syncthreads();

        float acc[4][4][4];
#pragma unroll
        for (int ma = 0; ma < 4; ma++)
#pragma unroll
            for (int na = 0; na < 4; na++)
#pragma unroll
                for (int c = 0; c < 4; c++) acc[ma][na][c] = 0.0f;

        float* const op = obase + (size_t)t * MT * HID;

        // --- flattened 64-step pipeline: j = ma*16 + ks
        //  - ldsm frag(j+1) each step (2-deep rotation)
        //  - ma=0 steps host the next-tile fill: LDG at j=0/12/24/36 was the
        //    plan, but j=12..36 span ma=0..2; epilogue pieces sit at
        //    ma>=1 && (ks&3)==3 (j=19,23,...), disjoint from 12/20/24/32/36/44.
        //  - epilogue of m-atom (ma-1) during ma's steps; tail = ma 3.
        uint32_t af[2][4];
        {
            const uint32_t row = (uint32_t)(l & 15);
            const uint32_t c16 = (uint32_t)(l >> 4);
            ldsm_x4(af[0], bufg + row * 512u + ((c16 ^ (row & 7u)) << 4));
        }
        float4 xb[4];
#pragma unroll
        for (int j = 0; j < 64; j++) {
            const int ma = j >> 4;
            const int ks = j & 15;
            if (j < 63) {
                const int jn = j + 1;
                const uint32_t row = (uint32_t)(((jn >> 4) << 4) + (l & 15));
                const uint32_t c16 = (uint32_t)(((jn & 15) << 1) + (l >> 4));
                ldsm_x4(af[jn & 1], bufg + row * 512u + ((c16 ^ (row & 7u)) << 4));
            }
            // next-tile fill weave (4 batches of 4 float4)
            if (have_next && (j == 0 || j == 12 || j == 24 || j == 36)) {
                const int base = (j / 12) * 4;
#pragma unroll
                for (int k = 0; k < 4; k++)
                    xb[k] = __ldcs(&nsrc[tid + (base + k) * NTHREADS]);
            } else if (have_next && (j == 8 || j == 20 || j == 32 || j == 44)) {
                const int base = ((j - 8) / 12) * 4;
#pragma unroll
                for (int k = 0; k < 4; k++)
                    cvt_store(bufc, tid + (base + k) * NTHREADS, xb[k]);
            } else if (ma >= 1 && (ks & 3) == 3) {
                // epilogue piece: acc[ma-1], na = ks>>2
                const int me = ma - 1, na = ks >> 2;
                float2 v0, v1;
                v0.x = tanh_f(acc[me][na][0] + bb[na].x);
                v0.y = tanh_f(acc[me][na][1] + bb[na].y);
                v1.x = tanh_f(acc[me][na][2] + bb[na].x);
                v1.y = tanh_f(acc[me][na][3] + bb[na].y);
                __stcs((float2*)(op + (size_t)me * 16 * HID + na * 8), v0);
                __stcs((float2*)(op + (size_t)(me * 16 + 8) * HID + na * 8), v1);
            }
#pragma unroll
            for (int na = 0; na < 4; na++)
                mma16816(acc[ma][na], af[j & 1], wreg[na][ks]);
        }

        // exposed tail: epilogue of ma = 3
#pragma unroll
        for (int na = 0; na < 4; na++) {
            float2 v0, v1;
            v0.x = tanh_f(acc[3][na][0] + bb[na].x);
            v0.y = tanh_f(acc[3][na][1] + bb[na].y);
            v1.x = tanh_f(acc[3][na][2] + bb[na].x);
            v1.y = tanh_f(acc[3][na][3] + bb[na].y);
            __stcs((float2*)(op + (size_t)48 * HID + na * 8), v0);
            __stcs((float2*)(op + (size_t)56 * HID + na * 8), v1);
        }
    }
}

// ----------------------------------------------------------------- launch ----

extern "C" void kernel_launch(void* const* d_in, const int* in_sizes, int n_in,
                              void* d_out, int out_size) {
    const float* x = (const float*)d_in[0];
    const float* W = (const float*)d_in[1];
    const float* b = (const float*)d_in[2];
    float* out = (float*)d_out;
    cudaFuncSetAttribute(rotor_kernel,
                         cudaFuncAttributeMaxDynamicSharedMemorySize, SMEM_TOTAL);
    rotor_kernel<<<GRID, NTHREADS, SMEM_TOTAL>>>(x, W, b, out);
}